// round 14
// baseline (speedup 1.0000x reference)
#include <cuda_runtime.h>
#include <cstdint>

// DCT_Layer: grouped conv, fixed separable 4x4 DCT basis, pad=2, min(|v|,8).
// x: (8,3,512,512) f32 -> out: (8,48,513,513) f32
//
// Persistent single-wave layout: grid (24, 24) = yb x bc, 576 blocks, all
// resident (4 CTAs/SM). Each block sweeps 5-6 consecutive 4-row y-groups of
// one image -> 16 plane write-streams advance sequentially ~41-49 KB each.
// Per tile: direct-gmem column pass -> sc[16][520]; 4 kk-groups of 128
// threads do the row pass with aligned float4 stores (compile-time shifts).
//   A[0]={.5,.5,.5,.5}; A[1]={a,b,-b,-a}; A[2]={.5,-.5,-.5,.5}; A[3]={b,-a,a,-b}

#define HIN   512
#define WIN   512
#define HOUT  513
#define WOUT  513
#define PLANE (HOUT * WOUT)   // 263169 (== 1 mod 4)
#define XCOL  520             // s-cols 0..519; input col = s-col - 2
#define CA 0.65328148243818826f
#define CB 0.27059805007309851f

__device__ __forceinline__ float t8(float v) { return fminf(fabsf(v), 8.0f); }

// 4-tap row DCT of window w at offset c (compile-time after unroll)
template<int LL>
__device__ __forceinline__ float rowdct(const float* __restrict__ w, int c) {
    if (LL == 0) return 0.5f * ((w[c] + w[c+1]) + (w[c+2] + w[c+3]));
    if (LL == 1) return CA * (w[c] - w[c+3]) + CB * (w[c+1] - w[c+2]);
    if (LL == 2) return 0.5f * ((w[c] + w[c+3]) - (w[c+1] + w[c+2]));
    return CB * (w[c] - w[c+3]) - CA * (w[c+1] - w[c+2]);
}

// One plane row: aligned float4 streaming store + edge columns.
// pl = plane base + y*513 + 4*tt; thread tt's window = s-cols 4tt..4tt+11.
template<int SH, int LL>
__device__ __forceinline__ void plane_out(const float* __restrict__ w,
                                          float* __restrict__ pl, int tt) {
    float4 v;
    v.x = t8(rowdct<LL>(w, SH + 0));
    v.y = t8(rowdct<LL>(w, SH + 1));
    v.z = t8(rowdct<LL>(w, SH + 2));
    v.w = t8(rowdct<LL>(w, SH + 3));
    if (SH <= 1 || tt < 127)
        __stcs(reinterpret_cast<float4*>(pl + SH), v);

    if (SH > 0 && tt == 0) {                 // left edge cols 0..SH-1
#pragma unroll
        for (int c = 0; c < SH; c++)
            pl[c] = t8(rowdct<LL>(w, c));
    }
    constexpr int NP = (WOUT - SH) >> 2;
    constexpr int RS = SH + 4 * NP;
    if (RS < WOUT && tt == 127) {            // right edge cols RS..512
#pragma unroll
        for (int c = RS; c < WOUT; c++)
            pl[c - 508] = t8(rowdct<LL>(w, c - 508));
    }
}

__shared__ float sc[16][XCOL];   // column DCT [kk*4+r][c]  (33,280 B)

// 4 planes of group kk for output row with (y % 4) == R; w = 12-col window
template<int R>
__device__ __forceinline__ void do_row(const float* __restrict__ w,
                                       float* __restrict__ pb, int tt) {
    plane_out<(4 - ((R + 0) & 3)) & 3, 0>(w, pb,                     tt);
    plane_out<(4 - ((R + 1) & 3)) & 3, 1>(w, pb + 1 * (size_t)PLANE, tt);
    plane_out<(4 - ((R + 2) & 3)) & 3, 2>(w, pb + 2 * (size_t)PLANE, tt);
    plane_out<(4 - ((R + 3) & 3)) & 3, 3>(w, pb + 3 * (size_t)PLANE, tt);
}

__global__ __launch_bounds__(512, 4)
void dct_layer_kernel(const float* __restrict__ x, float* __restrict__ out) {
    const int yb = blockIdx.x;       // 0..23
    const int bc = blockIdx.y;       // 0..23
    const int t  = threadIdx.x;

    // 129 y-groups over 24 blocks: first 9 blocks get 6, rest get 5 (consecutive)
    const int g0  = yb * 5 + min(yb, 9);
    const int cnt = 5 + (yb < 9 ? 1 : 0);

    const float* __restrict__ xp = x + (size_t)bc * (HIN * WIN);
    const int kk = t >> 7, tt = t & 127;
    float* __restrict__ pk = out + (size_t)(bc * 16 + kk * 4) * PLANE + 4 * tt;

    for (int g = 0; g < cnt; g++) {
        const int y0 = (g0 + g) * 4;
        if (g) __syncthreads();      // WAR: prev row pass done before sc rewrite

        // ---- column pass, direct from gmem (coalesced, L2-resident)
        for (int c = t; c < XCOL; c += 512) {
            const int ix = c - 2;
            const bool cok = (unsigned)ix < (unsigned)WIN;
            float v[7];
#pragma unroll
            for (int i = 0; i < 7; i++) {
                const int iy = y0 - 2 + i;
                v[i] = (cok && (unsigned)iy < (unsigned)HIN)
                           ? __ldg(xp + iy * WIN + ix) : 0.0f;
            }
#pragma unroll
            for (int r = 0; r < 4; r++) {
                float a = v[r], b = v[r+1], d = v[r+2], e = v[r+3];
                float p = a + e, q = b + d;
                float m = a - e, n = b - d;
                sc[ 0 + r][c] = 0.5f * (p + q);
                sc[ 4 + r][c] = CA * m + CB * n;
                sc[ 8 + r][c] = 0.5f * (p - q);
                sc[12 + r][c] = CB * m - CA * n;
            }
        }
        __syncthreads();

        // ---- row pass: group kk handles planes kk*4 .. kk*4+3
        float* __restrict__ pb = pk + (size_t)y0 * WOUT;
#pragma unroll
        for (int r = 0; r < 4; r++) {
            if (y0 + r < HOUT) {
                float w[12];
                const float4* __restrict__ s4 =
                    reinterpret_cast<const float4*>(&sc[kk * 4 + r][0]);
                float4 a = s4[tt], b = s4[tt + 1], c2 = s4[tt + 2];
                w[0] = a.x;  w[1] = a.y;  w[2]  = a.z;  w[3]  = a.w;
                w[4] = b.x;  w[5] = b.y;  w[6]  = b.z;  w[7]  = b.w;
                w[8] = c2.x; w[9] = c2.y; w[10] = c2.z; w[11] = c2.w;

                float* __restrict__ pr = pb + (size_t)r * WOUT;
                switch (r) {            // r literal under unroll; y%4 == r
                    case 0: do_row<0>(w, pr, tt); break;
                    case 1: do_row<1>(w, pr, tt); break;
                    case 2: do_row<2>(w, pr, tt); break;
                    default: do_row<3>(w, pr, tt); break;
                }
            }
        }
    }
}

extern "C" void kernel_launch(void* const* d_in, const int* in_sizes, int n_in,
                              void* d_out, int out_size) {
    const float* x = (const float*)d_in[0];
    float* out     = (float*)d_out;
    (void)in_sizes; (void)n_in; (void)out_size;

    dim3 grid(24, 24);   // yb x bc, 576 persistent blocks (single wave)
    dim3 block(512);
    dct_layer_kernel<<<grid, block>>>(x, out);
}

// round 15
// speedup vs baseline: 1.1454x; 1.1454x over previous
#include <cuda_runtime.h>
#include <cstdint>

// DCT_Layer: grouped conv, fixed separable 4x4 DCT basis, pad=2, min(|v|,8).
// x: (8,3,512,512) f32 -> out: (8,48,513,513) f32
//
// R6 champion structure (66.0us), single change: default stores (no __stcs)
// to let L2 aggregate dirty lines before DRAM drain.
// Block = 512 threads = 4 groups of 128; group kk owns planes kk*4+ll.
// 4 output rows per block (y0 % 4 == 0 -> all store shifts compile-time).
//   A[0]={.5,.5,.5,.5}; A[1]={a,b,-b,-a}; A[2]={.5,-.5,-.5,.5}; A[3]={b,-a,a,-b}

#define HIN   512
#define WIN   512
#define HOUT  513
#define WOUT  513
#define PLANE (HOUT * WOUT)   // 263169 (== 1 mod 4)
#define XCOL  520             // s-cols 0..519; input col = s-col - 2
#define CA 0.65328148243818826f
#define CB 0.27059805007309851f

__constant__ float c_A[4][4] = {
    { 0.5f,  0.5f,  0.5f,  0.5f },
    {  CA,    CB,   -CB,   -CA  },
    { 0.5f, -0.5f, -0.5f,  0.5f },
    {  CB,   -CA,    CA,   -CB  }
};

__device__ __forceinline__ float t8(float v) { return fminf(fabsf(v), 8.0f); }

// 4-tap row DCT of window w at offset c (compile-time after unroll)
template<int LL>
__device__ __forceinline__ float rowdct(const float* __restrict__ w, int c) {
    if (LL == 0) return 0.5f * ((w[c] + w[c+1]) + (w[c+2] + w[c+3]));
    if (LL == 1) return CA * (w[c] - w[c+3]) + CB * (w[c+1] - w[c+2]);
    if (LL == 2) return 0.5f * ((w[c] + w[c+3]) - (w[c+1] + w[c+2]));
    return CB * (w[c] - w[c+3]) - CA * (w[c+1] - w[c+2]);
}

// One plane row: aligned float4 store + edge columns.
// pl = plane base + y*513 + 4*tt; thread tt's window = s-cols 4tt..4tt+11.
template<int SH, int LL>
__device__ __forceinline__ void plane_out(const float* __restrict__ w,
                                          float* __restrict__ pl, int tt) {
    float4 v;
    v.x = t8(rowdct<LL>(w, SH + 0));
    v.y = t8(rowdct<LL>(w, SH + 1));
    v.z = t8(rowdct<LL>(w, SH + 2));
    v.w = t8(rowdct<LL>(w, SH + 3));
    if (SH <= 1 || tt < 127)
        *reinterpret_cast<float4*>(pl + SH) = v;   // default policy (was __stcs)

    if (SH > 0 && tt == 0) {                 // left edge cols 0..SH-1
#pragma unroll
        for (int c = 0; c < SH; c++)
            pl[c] = t8(rowdct<LL>(w, c));
    }
    constexpr int NP = (WOUT - SH) >> 2;
    constexpr int RS = SH + 4 * NP;
    if (RS < WOUT && tt == 127) {            // right edge cols RS..512
#pragma unroll
        for (int c = RS; c < WOUT; c++)
            pl[c - 508] = t8(rowdct<LL>(w, c - 508));
    }
}

// 4 planes of one kk for output row with (y % 4) == R
template<int R>
__device__ __forceinline__ void do_row(const float* __restrict__ w,
                                       float* __restrict__ pb, int tt) {
    plane_out<(4 - ((R + 0) & 3)) & 3, 0>(w, pb,                     tt);
    plane_out<(4 - ((R + 1) & 3)) & 3, 1>(w, pb + 1 * (size_t)PLANE, tt);
    plane_out<(4 - ((R + 2) & 3)) & 3, 2>(w, pb + 2 * (size_t)PLANE, tt);
    plane_out<(4 - ((R + 3) & 3)) & 3, 3>(w, pb + 3 * (size_t)PLANE, tt);
}

__global__ __launch_bounds__(512, 3)
void dct_layer_kernel(const float* __restrict__ x, float* __restrict__ out) {
    const int y0 = blockIdx.x * 4;   // 0,4,...,512
    const int bc = blockIdx.y;       // 0..23
    const int t  = threadIdx.x;

    __shared__ float xin[7][XCOL];   // input rows y0-2 .. y0+4, pitch 2080B

    const float* __restrict__ xp = x + (size_t)bc * (HIN * WIN);

    // ---- staging: 7 rows x 128 float4 = 896 predicated LDG.128
#pragma unroll
    for (int s = 0; s < 2; s++) {
        const int idx = t + s * 512;
        if (idx < 7 * 128) {
            const int row = idx >> 7, j = idx & 127;
            const int iy = y0 - 2 + row;
            float4 v = make_float4(0.f, 0.f, 0.f, 0.f);
            if ((unsigned)iy < (unsigned)HIN)
                v = *reinterpret_cast<const float4*>(xp + iy * WIN + 4 * j);
            float* xr = &xin[row][2 + 4 * j];
            xr[0] = v.x; xr[1] = v.y; xr[2] = v.z; xr[3] = v.w;
            if (j < 8)   // zero halo cols 0,1,514..519 of this row
                xin[row][(j < 2) ? j : (512 + j)] = 0.f;
        }
    }
    __syncthreads();

    const int kk = t >> 7, tt = t & 127;
    const float k0 = c_A[kk][0], k1 = c_A[kk][1], k2 = c_A[kk][2], k3 = c_A[kk][3];

    float* __restrict__ pb = out + (size_t)(bc * 16 + kk * 4) * PLANE
                                 + (size_t)y0 * WOUT + 4 * tt;

    // ---- 4 output rows; column DCT built in registers from xin
#pragma unroll
    for (int r = 0; r < 4; r++) {
        if (y0 + r < HOUT) {
            float acc[12];
#pragma unroll
            for (int i = 0; i < 4; i++) {
                const float4* __restrict__ s4 =
                    reinterpret_cast<const float4*>(&xin[r + i][0]);
                float4 a = s4[tt], b = s4[tt + 1], c = s4[tt + 2];
                float w[12] = { a.x, a.y, a.z, a.w,
                                b.x, b.y, b.z, b.w,
                                c.x, c.y, c.z, c.w };
                const float kc = (i == 0) ? k0 : (i == 1) ? k1 : (i == 2) ? k2 : k3;
                if (i == 0) {
#pragma unroll
                    for (int j = 0; j < 12; j++) acc[j] = kc * w[j];
                } else {
#pragma unroll
                    for (int j = 0; j < 12; j++) acc[j] = fmaf(kc, w[j], acc[j]);
                }
            }
            float* __restrict__ pr = pb + (size_t)r * WOUT;
            switch (r) {            // r is a literal under unroll
                case 0: do_row<0>(acc, pr, tt); break;
                case 1: do_row<1>(acc, pr, tt); break;
                case 2: do_row<2>(acc, pr, tt); break;
                default: do_row<3>(acc, pr, tt); break;
            }
        }
    }
}

extern "C" void kernel_launch(void* const* d_in, const int* in_sizes, int n_in,
                              void* d_out, int out_size) {
    const float* x = (const float*)d_in[0];
    float* out     = (float*)d_out;
    (void)in_sizes; (void)n_in; (void)out_size;

    dim3 grid((HOUT + 3) / 4, 8 * 3);   // (129, 24), ygroup fastest
    dim3 block(512);
    dct_layer_kernel<<<grid, block>>>(x, out);
}

// round 16
// speedup vs baseline: 1.2463x; 1.0881x over previous
#include <cuda_runtime.h>
#include <cstdint>

// DCT_Layer: grouped conv, fixed separable 4x4 DCT basis, pad=2, min(|v|,8).
// x: (8,3,512,512) f32 -> out: (8,48,513,513) f32
//
// FINAL (R6 champion, 66.0us): Block = 512 threads = 4 groups of 128; group
// kk owns planes kk*4+ll. 4 output rows per block (y0 % 4 == 0 -> all store
// alignment shifts compile-time), register column-DCT, aligned float4 __stcs.
//   A[0]={.5,.5,.5,.5}; A[1]={a,b,-b,-a}; A[2]={.5,-.5,-.5,.5}; A[3]={b,-a,a,-b}

#define HIN   512
#define WIN   512
#define HOUT  513
#define WOUT  513
#define PLANE (HOUT * WOUT)   // 263169 (== 1 mod 4)
#define XCOL  520             // s-cols 0..519; input col = s-col - 2
#define CA 0.65328148243818826f
#define CB 0.27059805007309851f

__constant__ float c_A[4][4] = {
    { 0.5f,  0.5f,  0.5f,  0.5f },
    {  CA,    CB,   -CB,   -CA  },
    { 0.5f, -0.5f, -0.5f,  0.5f },
    {  CB,   -CA,    CA,   -CB  }
};

__device__ __forceinline__ float t8(float v) { return fminf(fabsf(v), 8.0f); }

// 4-tap row DCT of window w at offset c (compile-time after unroll)
template<int LL>
__device__ __forceinline__ float rowdct(const float* __restrict__ w, int c) {
    if (LL == 0) return 0.5f * ((w[c] + w[c+1]) + (w[c+2] + w[c+3]));
    if (LL == 1) return CA * (w[c] - w[c+3]) + CB * (w[c+1] - w[c+2]);
    if (LL == 2) return 0.5f * ((w[c] + w[c+3]) - (w[c+1] + w[c+2]));
    return CB * (w[c] - w[c+3]) - CA * (w[c+1] - w[c+2]);
}

// One plane row: aligned float4 streaming store + edge columns.
// pl = plane base + y*513 + 4*tt; thread tt's window = s-cols 4tt..4tt+11.
template<int SH, int LL>
__device__ __forceinline__ void plane_out(const float* __restrict__ w,
                                          float* __restrict__ pl, int tt) {
    float4 v;
    v.x = t8(rowdct<LL>(w, SH + 0));
    v.y = t8(rowdct<LL>(w, SH + 1));
    v.z = t8(rowdct<LL>(w, SH + 2));
    v.w = t8(rowdct<LL>(w, SH + 3));
    if (SH <= 1 || tt < 127)
        __stcs(reinterpret_cast<float4*>(pl + SH), v);

    if (SH > 0 && tt == 0) {                 // left edge cols 0..SH-1
#pragma unroll
        for (int c = 0; c < SH; c++)
            pl[c] = t8(rowdct<LL>(w, c));
    }
    constexpr int NP = (WOUT - SH) >> 2;
    constexpr int RS = SH + 4 * NP;
    if (RS < WOUT && tt == 127) {            // right edge cols RS..512
#pragma unroll
        for (int c = RS; c < WOUT; c++)
            pl[c - 508] = t8(rowdct<LL>(w, c - 508));
    }
}

// 4 planes of one kk for output row with (y % 4) == R
template<int R>
__device__ __forceinline__ void do_row(const float* __restrict__ w,
                                       float* __restrict__ pb, int tt) {
    plane_out<(4 - ((R + 0) & 3)) & 3, 0>(w, pb,                     tt);
    plane_out<(4 - ((R + 1) & 3)) & 3, 1>(w, pb + 1 * (size_t)PLANE, tt);
    plane_out<(4 - ((R + 2) & 3)) & 3, 2>(w, pb + 2 * (size_t)PLANE, tt);
    plane_out<(4 - ((R + 3) & 3)) & 3, 3>(w, pb + 3 * (size_t)PLANE, tt);
}

__global__ __launch_bounds__(512, 3)
void dct_layer_kernel(const float* __restrict__ x, float* __restrict__ out) {
    const int y0 = blockIdx.x * 4;   // 0,4,...,512
    const int bc = blockIdx.y;       // 0..23
    const int t  = threadIdx.x;

    __shared__ float xin[7][XCOL];   // input rows y0-2 .. y0+4, pitch 2080B

    const float* __restrict__ xp = x + (size_t)bc * (HIN * WIN);

    // ---- staging: 7 rows x 128 float4 = 896 predicated LDG.128
#pragma unroll
    for (int s = 0; s < 2; s++) {
        const int idx = t + s * 512;
        if (idx < 7 * 128) {
            const int row = idx >> 7, j = idx & 127;
            const int iy = y0 - 2 + row;
            float4 v = make_float4(0.f, 0.f, 0.f, 0.f);
            if ((unsigned)iy < (unsigned)HIN)
                v = *reinterpret_cast<const float4*>(xp + iy * WIN + 4 * j);
            float* xr = &xin[row][2 + 4 * j];
            xr[0] = v.x; xr[1] = v.y; xr[2] = v.z; xr[3] = v.w;
            if (j < 8)   // zero halo cols 0,1,514..519 of this row
                xin[row][(j < 2) ? j : (512 + j)] = 0.f;
        }
    }
    __syncthreads();

    const int kk = t >> 7, tt = t & 127;
    const float k0 = c_A[kk][0], k1 = c_A[kk][1], k2 = c_A[kk][2], k3 = c_A[kk][3];

    float* __restrict__ pb = out + (size_t)(bc * 16 + kk * 4) * PLANE
                                 + (size_t)y0 * WOUT + 4 * tt;

    // ---- 4 output rows; column DCT built in registers from xin
#pragma unroll
    for (int r = 0; r < 4; r++) {
        if (y0 + r < HOUT) {
            float acc[12];
#pragma unroll
            for (int i = 0; i < 4; i++) {
                const float4* __restrict__ s4 =
                    reinterpret_cast<const float4*>(&xin[r + i][0]);
                float4 a = s4[tt], b = s4[tt + 1], c = s4[tt + 2];
                float w[12] = { a.x, a.y, a.z, a.w,
                                b.x, b.y, b.z, b.w,
                                c.x, c.y, c.z, c.w };
                const float kc = (i == 0) ? k0 : (i == 1) ? k1 : (i == 2) ? k2 : k3;
                if (i == 0) {
#pragma unroll
                    for (int j = 0; j < 12; j++) acc[j] = kc * w[j];
                } else {
#pragma unroll
                    for (int j = 0; j < 12; j++) acc[j] = fmaf(kc, w[j], acc[j]);
                }
            }
            float* __restrict__ pr = pb + (size_t)r * WOUT;
            switch (r) {            // r is a literal under unroll
                case 0: do_row<0>(acc, pr, tt); break;
                case 1: do_row<1>(acc, pr, tt); break;
                case 2: do_row<2>(acc, pr, tt); break;
                default: do_row<3>(acc, pr, tt); break;
            }
        }
    }
}

extern "C" void kernel_launch(void* const* d_in, const int* in_sizes, int n_in,
                              void* d_out, int out_size) {
    const float* x = (const float*)d_in[0];
    float* out     = (float*)d_out;
    (void)in_sizes; (void)n_in; (void)out_size;

    dim3 grid((HOUT + 3) / 4, 8 * 3);   // (129, 24)
    dim3 block(512);
    dct_layer_kernel<<<grid, block>>>(x, out);
}

// round 17
// speedup vs baseline: 1.2487x; 1.0019x over previous
#include <cuda_runtime.h>
#include <cstdint>

// DCT_Layer: grouped conv, fixed separable 4x4 DCT basis, pad=2, min(|v|,8).
// x: (8,3,512,512) f32 -> out: (8,48,513,513) f32
//
// FINAL (champion, 66.0us wall / 68.5us ncu, HBM 5.4 TB/s = write-drain floor):
// Block = 512 threads = 4 groups of 128; group kk owns planes kk*4+ll.
// 4 output rows per block (y0 % 4 == 0 -> all store alignment shifts are
// compile-time), register column-DCT, aligned float4 __stcs stores, edge
// columns handled by threads 0/127.
//   A[0]={.5,.5,.5,.5}; A[1]={a,b,-b,-a}; A[2]={.5,-.5,-.5,.5}; A[3]={b,-a,a,-b}

#define HIN   512
#define WIN   512
#define HOUT  513
#define WOUT  513
#define PLANE (HOUT * WOUT)   // 263169 (== 1 mod 4)
#define XCOL  520             // s-cols 0..519; input col = s-col - 2
#define CA 0.65328148243818826f
#define CB 0.27059805007309851f

__constant__ float c_A[4][4] = {
    { 0.5f,  0.5f,  0.5f,  0.5f },
    {  CA,    CB,   -CB,   -CA  },
    { 0.5f, -0.5f, -0.5f,  0.5f },
    {  CB,   -CA,    CA,   -CB  }
};

__device__ __forceinline__ float t8(float v) { return fminf(fabsf(v), 8.0f); }

// 4-tap row DCT of window w at offset c (compile-time after unroll)
template<int LL>
__device__ __forceinline__ float rowdct(const float* __restrict__ w, int c) {
    if (LL == 0) return 0.5f * ((w[c] + w[c+1]) + (w[c+2] + w[c+3]));
    if (LL == 1) return CA * (w[c] - w[c+3]) + CB * (w[c+1] - w[c+2]);
    if (LL == 2) return 0.5f * ((w[c] + w[c+3]) - (w[c+1] + w[c+2]));
    return CB * (w[c] - w[c+3]) - CA * (w[c+1] - w[c+2]);
}

// One plane row: aligned float4 streaming store + edge columns.
// pl = plane base + y*513 + 4*tt; thread tt's window = s-cols 4tt..4tt+11.
template<int SH, int LL>
__device__ __forceinline__ void plane_out(const float* __restrict__ w,
                                          float* __restrict__ pl, int tt) {
    float4 v;
    v.x = t8(rowdct<LL>(w, SH + 0));
    v.y = t8(rowdct<LL>(w, SH + 1));
    v.z = t8(rowdct<LL>(w, SH + 2));
    v.w = t8(rowdct<LL>(w, SH + 3));
    if (SH <= 1 || tt < 127)
        __stcs(reinterpret_cast<float4*>(pl + SH), v);

    if (SH > 0 && tt == 0) {                 // left edge cols 0..SH-1
#pragma unroll
        for (int c = 0; c < SH; c++)
            pl[c] = t8(rowdct<LL>(w, c));
    }
    constexpr int NP = (WOUT - SH) >> 2;
    constexpr int RS = SH + 4 * NP;
    if (RS < WOUT && tt == 127) {            // right edge cols RS..512
#pragma unroll
        for (int c = RS; c < WOUT; c++)
            pl[c - 508] = t8(rowdct<LL>(w, c - 508));
    }
}

// 4 planes of one kk for output row with (y % 4) == R
template<int R>
__device__ __forceinline__ void do_row(const float* __restrict__ w,
                                       float* __restrict__ pb, int tt) {
    plane_out<(4 - ((R + 0) & 3)) & 3, 0>(w, pb,                     tt);
    plane_out<(4 - ((R + 1) & 3)) & 3, 1>(w, pb + 1 * (size_t)PLANE, tt);
    plane_out<(4 - ((R + 2) & 3)) & 3, 2>(w, pb + 2 * (size_t)PLANE, tt);
    plane_out<(4 - ((R + 3) & 3)) & 3, 3>(w, pb + 3 * (size_t)PLANE, tt);
}

__global__ __launch_bounds__(512, 3)
void dct_layer_kernel(const float* __restrict__ x, float* __restrict__ out) {
    const int y0 = blockIdx.x * 4;   // 0,4,...,512
    const int bc = blockIdx.y;       // 0..23
    const int t  = threadIdx.x;

    __shared__ float xin[7][XCOL];   // input rows y0-2 .. y0+4, pitch 2080B

    const float* __restrict__ xp = x + (size_t)bc * (HIN * WIN);

    // ---- staging: 7 rows x 128 float4 = 896 predicated LDG.128
#pragma unroll
    for (int s = 0; s < 2; s++) {
        const int idx = t + s * 512;
        if (idx < 7 * 128) {
            const int row = idx >> 7, j = idx & 127;
            const int iy = y0 - 2 + row;
            float4 v = make_float4(0.f, 0.f, 0.f, 0.f);
            if ((unsigned)iy < (unsigned)HIN)
                v = *reinterpret_cast<const float4*>(xp + iy * WIN + 4 * j);
            float* xr = &xin[row][2 + 4 * j];
            xr[0] = v.x; xr[1] = v.y; xr[2] = v.z; xr[3] = v.w;
            if (j < 8)   // zero halo cols 0,1,514..519 of this row
                xin[row][(j < 2) ? j : (512 + j)] = 0.f;
        }
    }
    __syncthreads();

    const int kk = t >> 7, tt = t & 127;
    const float k0 = c_A[kk][0], k1 = c_A[kk][1], k2 = c_A[kk][2], k3 = c_A[kk][3];

    float* __restrict__ pb = out + (size_t)(bc * 16 + kk * 4) * PLANE
                                 + (size_t)y0 * WOUT + 4 * tt;

    // ---- 4 output rows; column DCT built in registers from xin
#pragma unroll
    for (int r = 0; r < 4; r++) {
        if (y0 + r < HOUT) {
            float acc[12];
#pragma unroll
            for (int i = 0; i < 4; i++) {
                const float4* __restrict__ s4 =
                    reinterpret_cast<const float4*>(&xin[r + i][0]);
                float4 a = s4[tt], b = s4[tt + 1], c = s4[tt + 2];
                float w[12] = { a.x, a.y, a.z, a.w,
                                b.x, b.y, b.z, b.w,
                                c.x, c.y, c.z, c.w };
                const float kc = (i == 0) ? k0 : (i == 1) ? k1 : (i == 2) ? k2 : k3;
                if (i == 0) {
#pragma unroll
                    for (int j = 0; j < 12; j++) acc[j] = kc * w[j];
                } else {
#pragma unroll
                    for (int j = 0; j < 12; j++) acc[j] = fmaf(kc, w[j], acc[j]);
                }
            }
            float* __restrict__ pr = pb + (size_t)r * WOUT;
            switch (r) {            // r is a literal under unroll
                case 0: do_row<0>(acc, pr, tt); break;
                case 1: do_row<1>(acc, pr, tt); break;
                case 2: do_row<2>(acc, pr, tt); break;
                default: do_row<3>(acc, pr, tt); break;
            }
        }
    }
}

extern "C" void kernel_launch(void* const* d_in, const int* in_sizes, int n_in,
                              void* d_out, int out_size) {
    const float* x = (const float*)d_in[0];
    float* out     = (float*)d_out;
    (void)in_sizes; (void)n_in; (void)out_size;

    dim3 grid((HOUT + 3) / 4, 8 * 3);   // (129, 24)
    dim3 block(512);
    dct_layer_kernel<<<grid, block>>>(x, out);
}